// round 8
// baseline (speedup 1.0000x reference)
#include <cuda_runtime.h>
#include <cstdint>

#define NB       4
#define NN       2048
#define CLAMP_V  10.0f

typedef unsigned long long ull;

// Scratch for G = H @ W^T, [NB*NN, 32] floats = 1 MB (no allocs allowed)
__device__ __align__(16) float g_G[NB * NN * 32];

// ---------------- packed f32x2 helpers (FFMA2 via PTX) ----------------
__device__ __forceinline__ ull ffma2(ull a, ull b, ull c) {
    ull d;
    asm("fma.rn.f32x2 %0, %1, %2, %3;" : "=l"(d) : "l"(a), "l"(b), "l"(c));
    return d;
}
__device__ __forceinline__ ull pack2(float x, float y) {
    ull r;
    asm("mov.b64 %0, {%1, %2};" : "=l"(r) : "f"(x), "f"(y));
    return r;
}
__device__ __forceinline__ float2 unpack2(ull v) {
    float2 f;
    asm("mov.b64 {%0, %1}, %2;" : "=f"(f.x), "=f"(f.y) : "l"(v));
    return f;
}
__device__ __forceinline__ float hadd2(ull v) {
    float2 f = unpack2(v);
    return f.x + f.y;
}
__device__ __forceinline__ uint32_t smem_u32(const void* p) {
    uint32_t a;
    asm("{ .reg .u64 t; cvta.to.shared.u64 t, %1; cvt.u32.u64 %0, t; }" : "=r"(a) : "l"(p));
    return a;
}
__device__ __forceinline__ void cp16(uint32_t dst, const void* src) {
    asm volatile("cp.async.cg.shared.global [%0], [%1], 16;" :: "r"(dst), "l"(src) : "memory");
}
#define CP_COMMIT() asm volatile("cp.async.commit_group;" ::: "memory")
#define CP_WAIT0()  asm volatile("cp.async.wait_group 0;" ::: "memory")

// ============================================================================
// Kernel 1: G[n][k] = sum_d H[n][d] * W[k][d]   (N=8192 rows, K=32, D=1024)
// 128 blocks x 256 threads. W staged ONCE (131KB smem, all of D); H chunks of
// 64 d double-buffered via cp.async (1 barrier per chunk). Thread: 2 rows x 4 k.
// FFMA2-issue floor per SM ≈ 16.4k cyc ≈ 9.4us.
// ============================================================================
#define WS_ROW 514                        // 512 d-pairs + pad (keeps 16B align)
#define HS_ROW 34                         // 32 d-pairs + pad (16B align)
#define SMEM1  ((32 * WS_ROW + 2 * 64 * HS_ROW) * 8)

__global__ __launch_bounds__(256)
void geom_proj_kernel(const float* __restrict__ H, const float* __restrict__ W) {
    extern __shared__ __align__(16) ull sm1[];
    ull* Ws  = sm1;                       // [32][WS_ROW] : all of W, d-pair packed
    ull* Hs0 = sm1 + 32 * WS_ROW;         // [64][HS_ROW] double buffer
    ull* Hs1 = Hs0 + 64 * HS_ROW;

    const int tid = threadIdx.x;
    const int kg  = tid & 7;              // k = 4*kg + q
    const int rg  = tid >> 3;             // rows 2*rg, 2*rg+1
    const int n0  = blockIdx.x * 64;

    const uint32_t ws_a  = smem_u32(sm1);
    const uint32_t hs_a0 = ws_a + 32 * WS_ROW * 8;
    const uint32_t hs_a1 = hs_a0 + 64 * HS_ROW * 8;

    // ---- stage all of W (32 rows x 512 16B units, coalesced) + H chunk 0
    #pragma unroll
    for (int p = 0; p < 32; p++)
        cp16(ws_a + (uint32_t)(p * WS_ROW + tid * 2) * 8, W + p * 1024 + tid * 4);
    #pragma unroll
    for (int p = 0; p < 4; p++) {
        int idx = tid + 256 * p;
        int row = idx >> 4, fc = idx & 15;
        cp16(hs_a0 + (uint32_t)(row * HS_ROW + fc * 2) * 8,
             H + (size_t)(n0 + row) * 1024 + fc * 4);
    }
    CP_COMMIT();

    ull acc[2][4];
    #pragma unroll
    for (int r = 0; r < 2; r++)
        #pragma unroll
        for (int q = 0; q < 4; q++) acc[r][q] = 0ULL;

    #pragma unroll 1
    for (int c = 0; c < 16; c++) {
        CP_WAIT0();
        __syncthreads();

        if (c < 15) {                      // prefetch next H chunk into other buf
            uint32_t dst = (c & 1) ? hs_a0 : hs_a1;
            #pragma unroll
            for (int p = 0; p < 4; p++) {
                int idx = tid + 256 * p;
                int row = idx >> 4, fc = idx & 15;
                cp16(dst + (uint32_t)(row * HS_ROW + fc * 2) * 8,
                     H + (size_t)(n0 + row) * 1024 + (c + 1) * 64 + fc * 4);
            }
            CP_COMMIT();
        }

        const ull* cur = (c & 1) ? Hs1 : Hs0;
        const ull* h0p = cur + (2 * rg) * HS_ROW;
        const ull* h1p = cur + (2 * rg + 1) * HS_ROW;
        const ull* wp  = Ws + c * 32;      // global d-pair base for this chunk

        #pragma unroll
        for (int dp = 0; dp < 32; dp++) {
            ull h0 = h0p[dp];
            ull h1 = h1p[dp];
            #pragma unroll
            for (int q = 0; q < 4; q++) {
                ull w = wp[(4 * kg + q) * WS_ROW + dp];
                acc[0][q] = ffma2(h0, w, acc[0][q]);
                acc[1][q] = ffma2(h1, w, acc[1][q]);
            }
        }
    }

    // ---- store G rows as float4 (k 4*kg..4*kg+3 contiguous)
    #pragma unroll
    for (int r = 0; r < 2; r++) {
        float4 v;
        v.x = hadd2(acc[r][0]);
        v.y = hadd2(acc[r][1]);
        v.z = hadd2(acc[r][2]);
        v.w = hadd2(acc[r][3]);
        *(float4*)&g_G[(size_t)(n0 + 2 * rg + r) * 32 + kg * 4] = v;
    }
}

// ============================================================================
// Kernel 2: out[b,i,j] = clamp(alpha*Bprev - beta*max(0, Gsq_i+Gsq_j-2*G_i.G_j))
// Grid (32,32,4) x 128 threads; tile 64x64; micro 8(i) x 4(j).
// G tiles row-major [row][kpair] -> operand fetch via LDS.128 (2 kpairs/load):
// 96 LDS.128 per 512 FFMA2 per thread; 3 CTAs/SM.
// ============================================================================
#define GROW 18    // 16 kpairs + pad 2 (16B-aligned rows, broadcast-friendly)

__global__ __launch_bounds__(128, 3)
void bias_update_kernel(const float* __restrict__ Bprev,
                        const float* __restrict__ alpha_p,
                        const float* __restrict__ beta_p,
                        float* __restrict__ Out) {
    __shared__ __align__(16) ull Gi[64][GROW];
    __shared__ __align__(16) ull Gj[64][GROW];
    __shared__ float gsqI[64];
    __shared__ float gsqJ[64];

    const int tid = threadIdx.x;
    const int tx  = tid & 15;      // j = tx + 16*jj
    const int ty  = tid >> 4;      // i = ty + 8*ii
    const int b   = blockIdx.z;
    const int i0  = blockIdx.y * 64;
    const int j0  = blockIdx.x * 64;

    // ---- stage G tiles (coalesced float4)
    const float4* __restrict__ G4 = (const float4*)g_G;
    const size_t baseI = ((size_t)b * NN + i0) * 8;   // float4 units (8/row)
    const size_t baseJ = ((size_t)b * NN + j0) * 8;

    #pragma unroll
    for (int p = 0; p < 4; p++) {
        int idx = tid + 128 * p;               // 0..511
        int row = idx >> 3, fc = idx & 7;
        float4 a = G4[baseI + idx];
        *(float4*)&Gi[row][fc * 2] = a;
        float4 c = G4[baseJ + idx];
        *(float4*)&Gj[row][fc * 2] = c;
    }
    __syncthreads();

    // ---- row squared-norms
    if (tid < 64) {
        float s = 0.f;
        #pragma unroll
        for (int kk = 0; kk < 16; kk++) {
            float2 v = unpack2(Gi[tid][kk]);
            s += v.x * v.x + v.y * v.y;
        }
        gsqI[tid] = s;
    } else {
        int t = tid - 64;
        float s = 0.f;
        #pragma unroll
        for (int kk = 0; kk < 16; kk++) {
            float2 v = unpack2(Gj[t][kk]);
            s += v.x * v.x + v.y * v.y;
        }
        gsqJ[t] = s;
    }
    __syncthreads();

    // ---- 8x4 Gram micro-tile, operands via LDS.128 (2 kpairs per load)
    ull acc[8][4];
    #pragma unroll
    for (int ii = 0; ii < 8; ii++)
        #pragma unroll
        for (int jj = 0; jj < 4; jj++) acc[ii][jj] = 0ULL;

    #pragma unroll
    for (int kk2 = 0; kk2 < 8; kk2++) {
        ull a0[8], a1[8], b0[4], b1[4];
        #pragma unroll
        for (int ii = 0; ii < 8; ii++) {
            float4 t = *(const float4*)&Gi[ty + 8 * ii][kk2 * 2];
            a0[ii] = pack2(t.x, t.y);
            a1[ii] = pack2(t.z, t.w);
        }
        #pragma unroll
        for (int jj = 0; jj < 4; jj++) {
            float4 t = *(const float4*)&Gj[tx + 16 * jj][kk2 * 2];
            b0[jj] = pack2(t.x, t.y);
            b1[jj] = pack2(t.z, t.w);
        }
        #pragma unroll
        for (int ii = 0; ii < 8; ii++)
            #pragma unroll
            for (int jj = 0; jj < 4; jj++) {
                acc[ii][jj] = ffma2(a0[ii], b0[jj], acc[ii][jj]);
                acc[ii][jj] = ffma2(a1[ii], b1[jj], acc[ii][jj]);
            }
    }

    // ---- fused EMA epilogue (per-row Bprev load batch -> compute -> store)
    const float alpha = __ldg(alpha_p);
    const float beta  = __ldg(beta_p);
    const size_t obase = (size_t)b * NN * NN;

    #pragma unroll
    for (int ii = 0; ii < 8; ii++) {
        const int row = i0 + ty + 8 * ii;
        const float si = gsqI[ty + 8 * ii];
        const float* __restrict__ bpr = Bprev + obase + (size_t)row * NN + j0;
        float* __restrict__ opr = Out + obase + (size_t)row * NN + j0;

        float bp[4];
        #pragma unroll
        for (int jj = 0; jj < 4; jj++)
            bp[jj] = __ldg(bpr + tx + 16 * jj);

        #pragma unroll
        for (int jj = 0; jj < 4; jj++) {
            float g = hadd2(acc[ii][jj]);
            float dist = si + gsqJ[tx + 16 * jj] - 2.0f * g;
            dist = fmaxf(dist, 0.0f);
            float v = alpha * bp[jj] - beta * dist;
            v = fminf(fmaxf(v, -CLAMP_V), CLAMP_V);
            opr[tx + 16 * jj] = v;
        }
    }
}

// ============================================================================
extern "C" void kernel_launch(void* const* d_in, const int* in_sizes, int n_in,
                              void* d_out, int out_size) {
    const float* H     = (const float*)d_in[0];   // [4,2048,1024]
    const float* Bprev = (const float*)d_in[1];   // [4,2048,2048]
    const float* W     = (const float*)d_in[2];   // [32,1024]
    const float* alpha = (const float*)d_in[3];   // scalar
    const float* beta  = (const float*)d_in[4];   // scalar
    float* Out = (float*)d_out;

    cudaFuncSetAttribute(geom_proj_kernel,
                         cudaFuncAttributeMaxDynamicSharedMemorySize, SMEM1);

    geom_proj_kernel<<<(NB * NN) / 64, 256, SMEM1>>>(H, W);
    bias_update_kernel<<<dim3(NN / 64, NN / 64, NB), 128>>>(Bprev, alpha, beta, Out);
}

// round 9
// speedup vs baseline: 1.9710x; 1.9710x over previous
#include <cuda_runtime.h>
#include <cstdint>

#define NB       4
#define NN       2048
#define CLAMP_V  10.0f

typedef unsigned long long ull;

// Partial G (2 d-halves): [2][NB*NN][32] floats = 2 MB (no allocs allowed)
__device__ __align__(16) float g_Gp[2 * NB * NN * 32];

// ---------------- packed f32x2 helpers (FFMA2 via PTX) ----------------
__device__ __forceinline__ ull ffma2(ull a, ull b, ull c) {
    ull d;
    asm("fma.rn.f32x2 %0, %1, %2, %3;" : "=l"(d) : "l"(a), "l"(b), "l"(c));
    return d;
}
__device__ __forceinline__ ull pack2(float x, float y) {
    ull r;
    asm("mov.b64 %0, {%1, %2};" : "=l"(r) : "f"(x), "f"(y));
    return r;
}
__device__ __forceinline__ float2 unpack2(ull v) {
    float2 f;
    asm("mov.b64 {%0, %1}, %2;" : "=f"(f.x), "=f"(f.y) : "l"(v));
    return f;
}
__device__ __forceinline__ float hadd2(ull v) {
    float2 f = unpack2(v);
    return f.x + f.y;
}
__device__ __forceinline__ uint32_t smem_u32(const void* p) {
    uint32_t a;
    asm("{ .reg .u64 t; cvta.to.shared.u64 t, %1; cvt.u32.u64 %0, t; }" : "=r"(a) : "l"(p));
    return a;
}
__device__ __forceinline__ void cp16(uint32_t dst, const void* src) {
    asm volatile("cp.async.cg.shared.global [%0], [%1], 16;" :: "r"(dst), "l"(src) : "memory");
}
#define CP_COMMIT() asm volatile("cp.async.commit_group;" ::: "memory")
#define CP_WAIT0()  asm volatile("cp.async.wait_group 0;" ::: "memory")

// ============================================================================
// Kernel 1: partial G[h][n][k] = sum_{d in half h} H[n][d] * W[k][d]
// 128 blocks (64 row-tiles x 2 d-halves) x 128 threads.
// Tile 128 rows x 32 k; chunk = 32 d (16 dpairs), 16 chunks per half.
// H double-buffered via cp.async; W chunk transposed to Ws[dp][k] via regs.
// Micro 8 rows x 4 k (k = kg + 8q, strided): h = LDS.128, w = LDS.64 (both
// conflict-free). 48 wf per 64 warp-FFMA2.
// ============================================================================
#define HROW 18   // ull per H row (16 dpairs + pad 2)
#define WROW 34   // ull per Ws row (32 k + pad 2)

__global__ __launch_bounds__(128)
void geom_proj_kernel(const float* __restrict__ H, const float* __restrict__ W) {
    __shared__ ull Hs[2][128][HROW];
    __shared__ ull Ws[2][16][WROW];

    const int tid  = threadIdx.x;
    const int kg   = tid & 7;          // k = kg + 8q
    const int ty   = tid >> 3;         // rows ty + 16*r  (0..15)
    const int half = blockIdx.x & 1;
    const int n0   = (blockIdx.x >> 1) * 128;
    const int dbase = half * 512;      // float offset

    const float4* __restrict__ W4 = (const float4*)W;
    const uint32_t hsb = smem_u32(&Hs[0][0][0]);

    // ---- prologue: cp.async H chunk 0, LDG W chunk 0
    #pragma unroll
    for (int p = 0; p < 8; p++) {
        int idx = tid + 128 * p;       // 0..1023
        int row = idx >> 3, fc = idx & 7;
        cp16(hsb + (uint32_t)((row) * HROW + fc * 2) * 8,
             H + (size_t)(n0 + row) * 1024 + dbase + fc * 4);
    }
    CP_COMMIT();

    float4 wr[2];
    #pragma unroll
    for (int p = 0; p < 2; p++) {
        int idx = tid + 128 * p;       // 0..255
        int k = idx >> 3, fs = idx & 7;
        wr[p] = W4[k * 256 + half * 128 + fs];
    }

    ull acc[8][4];
    #pragma unroll
    for (int r = 0; r < 8; r++)
        #pragma unroll
        for (int q = 0; q < 4; q++) acc[r][q] = 0ULL;

    #pragma unroll 1
    for (int c = 0; c < 16; c++) {
        const int buf = c & 1;
        CP_WAIT0();
        __syncthreads();

        // transpose-stage W chunk c: Ws[dp][k]
        #pragma unroll
        for (int p = 0; p < 2; p++) {
            int idx = tid + 128 * p;
            int k = idx >> 3, fs = idx & 7;
            Ws[buf][fs * 2][k]     = pack2(wr[p].x, wr[p].y);
            Ws[buf][fs * 2 + 1][k] = pack2(wr[p].z, wr[p].w);
        }

        if (c < 15) {                  // prefetch chunk c+1
            #pragma unroll
            for (int p = 0; p < 8; p++) {
                int idx = tid + 128 * p;
                int row = idx >> 3, fc = idx & 7;
                cp16(hsb + (uint32_t)(((1 - buf) * 128 + row) * HROW + fc * 2) * 8,
                     H + (size_t)(n0 + row) * 1024 + dbase + (c + 1) * 32 + fc * 4);
            }
            CP_COMMIT();
            #pragma unroll
            for (int p = 0; p < 2; p++) {
                int idx = tid + 128 * p;
                int k = idx >> 3, fs = idx & 7;
                wr[p] = W4[k * 256 + half * 128 + (c + 1) * 8 + fs];
            }
        }
        __syncthreads();

        #pragma unroll
        for (int dp2 = 0; dp2 < 8; dp2++) {
            ull w0[4], w1[4];
            #pragma unroll
            for (int q = 0; q < 4; q++) {
                w0[q] = Ws[buf][2 * dp2][kg + 8 * q];
                w1[q] = Ws[buf][2 * dp2 + 1][kg + 8 * q];
            }
            #pragma unroll
            for (int r = 0; r < 8; r++) {
                float4 hv = *(const float4*)&Hs[buf][ty + 16 * r][2 * dp2];
                ull hA = pack2(hv.x, hv.y);
                ull hB = pack2(hv.z, hv.w);
                #pragma unroll
                for (int q = 0; q < 4; q++) {
                    acc[r][q] = ffma2(hA, w0[q], acc[r][q]);
                    acc[r][q] = ffma2(hB, w1[q], acc[r][q]);
                }
            }
        }
    }

    // ---- store partial G
    float* __restrict__ Gp = g_Gp + (size_t)half * (NB * NN * 32);
    #pragma unroll
    for (int r = 0; r < 8; r++) {
        const size_t rb = (size_t)(n0 + ty + 16 * r) * 32;
        #pragma unroll
        for (int q = 0; q < 4; q++)
            Gp[rb + kg + 8 * q] = hadd2(acc[r][q]);
    }
}

// ============================================================================
// Kernel 2: triangular-symmetric EMA bias update.
// Grid (528, 4): q -> (ti, tj), tj <= ti; block = 64x64 dist tile; 128 threads,
// micro 8(i) x 4(j). Pass1 writes (i-tile, j-tile) from registers; pass2
// (off-diag only) writes (j-tile, i-tile) reading dist from padded smem.
// ============================================================================
#define GROW 18    // 16 kpairs + pad 2

__global__ __launch_bounds__(128, 3)
void bias_update_kernel(const float* __restrict__ Bprev,
                        const float* __restrict__ alpha_p,
                        const float* __restrict__ beta_p,
                        float* __restrict__ Out) {
    __shared__ __align__(16) ull Gi[64][GROW];
    __shared__ __align__(16) ull Gj[64][GROW];
    __shared__ float gsqI[64];
    __shared__ float gsqJ[64];
    __shared__ float dist_s[64][65];

    const int tid = threadIdx.x;
    const int tx  = tid & 15;      // j = tx + 16*jj
    const int ty  = tid >> 4;      // i = ty + 8*ii
    const int b   = blockIdx.y;

    // triangular decode: q -> (ti, tj), tj <= ti
    const int q = blockIdx.x;
    int ti = (int)((sqrtf(8.0f * (float)q + 1.0f) - 1.0f) * 0.5f);
    while ((ti + 1) * (ti + 2) / 2 <= q) ti++;
    while (ti * (ti + 1) / 2 > q) ti--;
    const int tj = q - ti * (ti + 1) / 2;
    const int i0 = ti * 64;
    const int j0 = tj * 64;
    const bool offd = (ti != tj);

    // ---- stage G tiles (sum of the two d-split partials)
    const float4* __restrict__ P0 = (const float4*)g_Gp;
    const float4* __restrict__ P1 = P0 + (NB * NN * 32) / 4;
    const size_t baseI = ((size_t)b * NN + i0) * 8;   // float4 units (8/row)
    const size_t baseJ = ((size_t)b * NN + j0) * 8;

    #pragma unroll
    for (int p = 0; p < 4; p++) {
        int idx = tid + 128 * p;               // 0..511
        int row = idx >> 3, fc = idx & 7;
        float4 a0 = P0[baseI + idx];
        float4 a1 = P1[baseI + idx];
        float4 s;
        s.x = a0.x + a1.x; s.y = a0.y + a1.y; s.z = a0.z + a1.z; s.w = a0.w + a1.w;
        *(float4*)&Gi[row][fc * 2] = s;
        float4 b0 = P0[baseJ + idx];
        float4 b1 = P1[baseJ + idx];
        float4 t;
        t.x = b0.x + b1.x; t.y = b0.y + b1.y; t.z = b0.z + b1.z; t.w = b0.w + b1.w;
        *(float4*)&Gj[row][fc * 2] = t;
    }
    __syncthreads();

    // ---- row squared-norms
    if (tid < 64) {
        float s = 0.f;
        #pragma unroll
        for (int kk = 0; kk < 16; kk++) {
            float2 v = unpack2(Gi[tid][kk]);
            s += v.x * v.x + v.y * v.y;
        }
        gsqI[tid] = s;
    } else {
        int t = tid - 64;
        float s = 0.f;
        #pragma unroll
        for (int kk = 0; kk < 16; kk++) {
            float2 v = unpack2(Gj[t][kk]);
            s += v.x * v.x + v.y * v.y;
        }
        gsqJ[t] = s;
    }
    __syncthreads();

    // ---- 8x4 Gram micro-tile (operands via LDS.128, 2 kpairs per load)
    ull acc[8][4];
    #pragma unroll
    for (int ii = 0; ii < 8; ii++)
        #pragma unroll
        for (int jj = 0; jj < 4; jj++) acc[ii][jj] = 0ULL;

    #pragma unroll
    for (int kk2 = 0; kk2 < 8; kk2++) {
        ull a0[8], a1[8], b0[4], b1[4];
        #pragma unroll
        for (int ii = 0; ii < 8; ii++) {
            float4 t = *(const float4*)&Gi[ty + 8 * ii][kk2 * 2];
            a0[ii] = pack2(t.x, t.y);
            a1[ii] = pack2(t.z, t.w);
        }
        #pragma unroll
        for (int jj = 0; jj < 4; jj++) {
            float4 t = *(const float4*)&Gj[tx + 16 * jj][kk2 * 2];
            b0[jj] = pack2(t.x, t.y);
            b1[jj] = pack2(t.z, t.w);
        }
        #pragma unroll
        for (int ii = 0; ii < 8; ii++)
            #pragma unroll
            for (int jj = 0; jj < 4; jj++) {
                acc[ii][jj] = ffma2(a0[ii], b0[jj], acc[ii][jj]);
                acc[ii][jj] = ffma2(a1[ii], b1[jj], acc[ii][jj]);
            }
    }

    const float alpha = __ldg(alpha_p);
    const float beta  = __ldg(beta_p);
    const size_t obase = (size_t)b * NN * NN;

    // ---- pass 1: rows in i-tile, cols in j-tile (dist from registers)
    #pragma unroll
    for (int ii = 0; ii < 8; ii++) {
        const int il = ty + 8 * ii;
        const int row = i0 + il;
        const float si = gsqI[il];
        const float* __restrict__ bpr = Bprev + obase + (size_t)row * NN + j0;
        float* __restrict__ opr = Out + obase + (size_t)row * NN + j0;

        float bp[4];
        #pragma unroll
        for (int jj = 0; jj < 4; jj++)
            bp[jj] = __ldg(bpr + tx + 16 * jj);

        #pragma unroll
        for (int jj = 0; jj < 4; jj++) {
            const int jl = tx + 16 * jj;
            float g = hadd2(acc[ii][jj]);
            float dist = si + gsqJ[jl] - 2.0f * g;
            dist = fmaxf(dist, 0.0f);
            if (offd) dist_s[il][jl] = dist;
            float v = alpha * bp[jj] - beta * dist;
            v = fminf(fmaxf(v, -CLAMP_V), CLAMP_V);
            opr[jl] = v;
        }
    }

    // ---- pass 2 (off-diagonal): rows in j-tile, cols in i-tile
    if (offd) {
        __syncthreads();
        #pragma unroll
        for (int rr = 0; rr < 8; rr++) {
            const int jl = ty + 8 * rr;
            const int row = j0 + jl;
            const float* __restrict__ bpr = Bprev + obase + (size_t)row * NN + i0;
            float* __restrict__ opr = Out + obase + (size_t)row * NN + i0;

            float bp[4];
            #pragma unroll
            for (int cc = 0; cc < 4; cc++)
                bp[cc] = __ldg(bpr + tx + 16 * cc);

            #pragma unroll
            for (int cc = 0; cc < 4; cc++) {
                const int il = tx + 16 * cc;
                float dist = dist_s[il][jl];
                float v = alpha * bp[cc] - beta * dist;
                v = fminf(fmaxf(v, -CLAMP_V), CLAMP_V);
                opr[il] = v;
            }
        }
    }
}

// ============================================================================
extern "C" void kernel_launch(void* const* d_in, const int* in_sizes, int n_in,
                              void* d_out, int out_size) {
    const float* H     = (const float*)d_in[0];   // [4,2048,1024]
    const float* Bprev = (const float*)d_in[1];   // [4,2048,2048]
    const float* W     = (const float*)d_in[2];   // [32,1024]
    const float* alpha = (const float*)d_in[3];   // scalar
    const float* beta  = (const float*)d_in[4];   // scalar
    float* Out = (float*)d_out;

    geom_proj_kernel<<<128, 128>>>(H, W);
    bias_update_kernel<<<dim3(528, NB), 128>>>(Bprev, alpha, beta, Out);
}

// round 10
// speedup vs baseline: 2.0176x; 1.0237x over previous
#include <cuda_runtime.h>
#include <cstdint>

#define NB       4
#define NN       2048
#define CLAMP_V  10.0f

typedef unsigned long long ull;

// Partial G (4 d-quarters): [4][NB*NN][32] floats = 4 MB (no allocs allowed)
__device__ __align__(16) float g_Gp[4 * NB * NN * 32];

// ---------------- packed f32x2 helpers (FFMA2 via PTX) ----------------
__device__ __forceinline__ ull ffma2(ull a, ull b, ull c) {
    ull d;
    asm("fma.rn.f32x2 %0, %1, %2, %3;" : "=l"(d) : "l"(a), "l"(b), "l"(c));
    return d;
}
__device__ __forceinline__ ull pack2(float x, float y) {
    ull r;
    asm("mov.b64 %0, {%1, %2};" : "=l"(r) : "f"(x), "f"(y));
    return r;
}
__device__ __forceinline__ float2 unpack2(ull v) {
    float2 f;
    asm("mov.b64 {%0, %1}, %2;" : "=f"(f.x), "=f"(f.y) : "l"(v));
    return f;
}
__device__ __forceinline__ float hadd2(ull v) {
    float2 f = unpack2(v);
    return f.x + f.y;
}
__device__ __forceinline__ uint32_t smem_u32(const void* p) {
    uint32_t a;
    asm("{ .reg .u64 t; cvta.to.shared.u64 t, %1; cvt.u32.u64 %0, t; }" : "=r"(a) : "l"(p));
    return a;
}
__device__ __forceinline__ void cp16(uint32_t dst, const void* src) {
    asm volatile("cp.async.cg.shared.global [%0], [%1], 16;" :: "r"(dst), "l"(src) : "memory");
}
#define CP_COMMIT() asm volatile("cp.async.commit_group;" ::: "memory")
#define CP_WAIT0()  asm volatile("cp.async.wait_group 0;" ::: "memory")

// ============================================================================
// Kernel 1: partial G[q][n][k] = sum_{d in quarter q} H[n][d] * W[k][d]
// 256 blocks (64 row-tiles x 4 d-quarters) x 128 threads -> 2 CTAs/SM resident.
// Tile 128 rows x 32 k; chunk = 32 d (16 dpairs), 8 chunks per quarter.
// H double-buffered via cp.async; W chunk transposed to Ws[dp][k] via regs.
// Micro 8 rows x 4 k (k = kg + 8q, strided).
// ============================================================================
#define HROW 18   // ull per H row (16 dpairs + pad 2)
#define WROW 34   // ull per Ws row (32 k + pad 2)

__global__ __launch_bounds__(128)
void geom_proj_kernel(const float* __restrict__ H, const float* __restrict__ W) {
    __shared__ ull Hs[2][128][HROW];
    __shared__ ull Ws[2][16][WROW];

    const int tid  = threadIdx.x;
    const int kg   = tid & 7;          // k = kg + 8q
    const int ty   = tid >> 3;         // rows ty + 16*r  (0..15)
    const int quar = blockIdx.x & 3;
    const int n0   = (blockIdx.x >> 2) * 128;
    const int dbase = quar * 256;      // float offset

    const float4* __restrict__ W4 = (const float4*)W;
    const uint32_t hsb = smem_u32(&Hs[0][0][0]);

    // ---- prologue: cp.async H chunk 0, LDG W chunk 0
    #pragma unroll
    for (int p = 0; p < 8; p++) {
        int idx = tid + 128 * p;       // 0..1023
        int row = idx >> 3, fc = idx & 7;
        cp16(hsb + (uint32_t)((row) * HROW + fc * 2) * 8,
             H + (size_t)(n0 + row) * 1024 + dbase + fc * 4);
    }
    CP_COMMIT();

    float4 wr[2];
    #pragma unroll
    for (int p = 0; p < 2; p++) {
        int idx = tid + 128 * p;       // 0..255
        int k = idx >> 3, fs = idx & 7;
        wr[p] = W4[k * 256 + quar * 64 + fs];
    }

    ull acc[8][4];
    #pragma unroll
    for (int r = 0; r < 8; r++)
        #pragma unroll
        for (int q = 0; q < 4; q++) acc[r][q] = 0ULL;

    #pragma unroll 1
    for (int c = 0; c < 8; c++) {
        const int buf = c & 1;
        CP_WAIT0();
        __syncthreads();

        // transpose-stage W chunk c: Ws[dp][k]
        #pragma unroll
        for (int p = 0; p < 2; p++) {
            int idx = tid + 128 * p;
            int k = idx >> 3, fs = idx & 7;
            Ws[buf][fs * 2][k]     = pack2(wr[p].x, wr[p].y);
            Ws[buf][fs * 2 + 1][k] = pack2(wr[p].z, wr[p].w);
        }

        if (c < 7) {                   // prefetch chunk c+1
            #pragma unroll
            for (int p = 0; p < 8; p++) {
                int idx = tid + 128 * p;
                int row = idx >> 3, fc = idx & 7;
                cp16(hsb + (uint32_t)(((1 - buf) * 128 + row) * HROW + fc * 2) * 8,
                     H + (size_t)(n0 + row) * 1024 + dbase + (c + 1) * 32 + fc * 4);
            }
            CP_COMMIT();
            #pragma unroll
            for (int p = 0; p < 2; p++) {
                int idx = tid + 128 * p;
                int k = idx >> 3, fs = idx & 7;
                wr[p] = W4[k * 256 + quar * 64 + (c + 1) * 8 + fs];
            }
        }
        __syncthreads();

        #pragma unroll
        for (int dp2 = 0; dp2 < 8; dp2++) {
            ull w0[4], w1[4];
            #pragma unroll
            for (int q = 0; q < 4; q++) {
                w0[q] = Ws[buf][2 * dp2][kg + 8 * q];
                w1[q] = Ws[buf][2 * dp2 + 1][kg + 8 * q];
            }
            #pragma unroll
            for (int r = 0; r < 8; r++) {
                float4 hv = *(const float4*)&Hs[buf][ty + 16 * r][2 * dp2];
                ull hA = pack2(hv.x, hv.y);
                ull hB = pack2(hv.z, hv.w);
                #pragma unroll
                for (int q = 0; q < 4; q++) {
                    acc[r][q] = ffma2(hA, w0[q], acc[r][q]);
                    acc[r][q] = ffma2(hB, w1[q], acc[r][q]);
                }
            }
        }
    }

    // ---- store partial G
    float* __restrict__ Gp = g_Gp + (size_t)quar * (NB * NN * 32);
    #pragma unroll
    for (int r = 0; r < 8; r++) {
        const size_t rb = (size_t)(n0 + ty + 16 * r) * 32;
        #pragma unroll
        for (int q = 0; q < 4; q++)
            Gp[rb + kg + 8 * q] = hadd2(acc[r][q]);
    }
}

// ============================================================================
// Kernel 2: triangular-symmetric EMA bias update.
// Grid (528, 4): q -> (ti, tj), tj <= ti; block = 64x64 dist tile; 128 threads,
// micro 8(i) x 4(j). Register-lean Gram loop (b staged, a just-in-time) to fit
// 4 CTAs/SM. Pass1 writes (i,j) from registers; pass2 (off-diag) writes (j,i)
// via padded smem dist tile.
// ============================================================================
#define GROW 18    // 16 kpairs + pad 2

__global__ __launch_bounds__(128, 4)
void bias_update_kernel(const float* __restrict__ Bprev,
                        const float* __restrict__ alpha_p,
                        const float* __restrict__ beta_p,
                        float* __restrict__ Out) {
    __shared__ __align__(16) ull Gi[64][GROW];
    __shared__ __align__(16) ull Gj[64][GROW];
    __shared__ float gsqI[64];
    __shared__ float gsqJ[64];
    __shared__ float dist_s[64][65];

    const int tid = threadIdx.x;
    const int tx  = tid & 15;      // j = tx + 16*jj
    const int ty  = tid >> 4;      // i = ty + 8*ii
    const int b   = blockIdx.y;

    // triangular decode: q -> (ti, tj), tj <= ti
    const int q = blockIdx.x;
    int ti = (int)((sqrtf(8.0f * (float)q + 1.0f) - 1.0f) * 0.5f);
    while ((ti + 1) * (ti + 2) / 2 <= q) ti++;
    while (ti * (ti + 1) / 2 > q) ti--;
    const int tj = q - ti * (ti + 1) / 2;
    const int i0 = ti * 64;
    const int j0 = tj * 64;
    const bool offd = (ti != tj);

    // ---- stage G tiles (sum of the four d-split partials)
    const float4* __restrict__ P0 = (const float4*)g_Gp;
    const float4* __restrict__ P1 = P0 + (NB * NN * 32) / 4;
    const float4* __restrict__ P2 = P1 + (NB * NN * 32) / 4;
    const float4* __restrict__ P3 = P2 + (NB * NN * 32) / 4;
    const size_t baseI = ((size_t)b * NN + i0) * 8;   // float4 units (8/row)
    const size_t baseJ = ((size_t)b * NN + j0) * 8;

    #pragma unroll
    for (int p = 0; p < 4; p++) {
        int idx = tid + 128 * p;               // 0..511
        int row = idx >> 3, fc = idx & 7;
        float4 a0 = P0[baseI + idx];
        float4 a1 = P1[baseI + idx];
        float4 a2 = P2[baseI + idx];
        float4 a3 = P3[baseI + idx];
        float4 s;
        s.x = (a0.x + a1.x) + (a2.x + a3.x);
        s.y = (a0.y + a1.y) + (a2.y + a3.y);
        s.z = (a0.z + a1.z) + (a2.z + a3.z);
        s.w = (a0.w + a1.w) + (a2.w + a3.w);
        *(float4*)&Gi[row][fc * 2] = s;
        float4 b0 = P0[baseJ + idx];
        float4 b1 = P1[baseJ + idx];
        float4 b2 = P2[baseJ + idx];
        float4 b3 = P3[baseJ + idx];
        float4 t;
        t.x = (b0.x + b1.x) + (b2.x + b3.x);
        t.y = (b0.y + b1.y) + (b2.y + b3.y);
        t.z = (b0.z + b1.z) + (b2.z + b3.z);
        t.w = (b0.w + b1.w) + (b2.w + b3.w);
        *(float4*)&Gj[row][fc * 2] = t;
    }
    __syncthreads();

    // ---- row squared-norms
    if (tid < 64) {
        float s = 0.f;
        #pragma unroll
        for (int kk = 0; kk < 16; kk++) {
            float2 v = unpack2(Gi[tid][kk]);
            s += v.x * v.x + v.y * v.y;
        }
        gsqI[tid] = s;
    } else {
        int t = tid - 64;
        float s = 0.f;
        #pragma unroll
        for (int kk = 0; kk < 16; kk++) {
            float2 v = unpack2(Gj[t][kk]);
            s += v.x * v.x + v.y * v.y;
        }
        gsqJ[t] = s;
    }
    __syncthreads();

    // ---- 8x4 Gram micro-tile, register-lean: b staged (8 ull), a just-in-time
    ull acc[8][4];
    #pragma unroll
    for (int ii = 0; ii < 8; ii++)
        #pragma unroll
        for (int jj = 0; jj < 4; jj++) acc[ii][jj] = 0ULL;

    #pragma unroll
    for (int kk2 = 0; kk2 < 8; kk2++) {
        ull b0[4], b1[4];
        #pragma unroll
        for (int jj = 0; jj < 4; jj++) {
            float4 t = *(const float4*)&Gj[tx + 16 * jj][kk2 * 2];
            b0[jj] = pack2(t.x, t.y);
            b1[jj] = pack2(t.z, t.w);
        }
        #pragma unroll
        for (int ii = 0; ii < 8; ii++) {
            float4 t = *(const float4*)&Gi[ty + 8 * ii][kk2 * 2];
            ull a0 = pack2(t.x, t.y);
            ull a1 = pack2(t.z, t.w);
            #pragma unroll
            for (int jj = 0; jj < 4; jj++) {
                acc[ii][jj] = ffma2(a0, b0[jj], acc[ii][jj]);
                acc[ii][jj] = ffma2(a1, b1[jj], acc[ii][jj]);
            }
        }
    }

    const float alpha = __ldg(alpha_p);
    const float beta  = __ldg(beta_p);
    const size_t obase = (size_t)b * NN * NN;

    // ---- pass 1: rows in i-tile, cols in j-tile (dist from registers)
    #pragma unroll
    for (int ii = 0; ii < 8; ii++) {
        const int il = ty + 8 * ii;
        const int row = i0 + il;
        const float si = gsqI[il];
        const float* __restrict__ bpr = Bprev + obase + (size_t)row * NN + j0;
        float* __restrict__ opr = Out + obase + (size_t)row * NN + j0;

        float bp[4];
        #pragma unroll
        for (int jj = 0; jj < 4; jj++)
            bp[jj] = __ldg(bpr + tx + 16 * jj);

        #pragma unroll
        for (int jj = 0; jj < 4; jj++) {
            const int jl = tx + 16 * jj;
            float g = hadd2(acc[ii][jj]);
            float dist = si + gsqJ[jl] - 2.0f * g;
            dist = fmaxf(dist, 0.0f);
            if (offd) dist_s[il][jl] = dist;
            float v = alpha * bp[jj] - beta * dist;
            v = fminf(fmaxf(v, -CLAMP_V), CLAMP_V);
            opr[jl] = v;
        }
    }

    // ---- pass 2 (off-diagonal): rows in j-tile, cols in i-tile
    if (offd) {
        __syncthreads();
        #pragma unroll
        for (int rr = 0; rr < 8; rr++) {
            const int jl = ty + 8 * rr;
            const int row = j0 + jl;
            const float* __restrict__ bpr = Bprev + obase + (size_t)row * NN + i0;
            float* __restrict__ opr = Out + obase + (size_t)row * NN + i0;

            float bp[4];
            #pragma unroll
            for (int cc = 0; cc < 4; cc++)
                bp[cc] = __ldg(bpr + tx + 16 * cc);

            #pragma unroll
            for (int cc = 0; cc < 4; cc++) {
                const int il = tx + 16 * cc;
                float dist = dist_s[il][jl];
                float v = alpha * bp[cc] - beta * dist;
                v = fminf(fmaxf(v, -CLAMP_V), CLAMP_V);
                opr[il] = v;
            }
        }
    }
}

// ============================================================================
extern "C" void kernel_launch(void* const* d_in, const int* in_sizes, int n_in,
                              void* d_out, int out_size) {
    const float* H     = (const float*)d_in[0];   // [4,2048,1024]
    const float* Bprev = (const float*)d_in[1];   // [4,2048,2048]
    const float* W     = (const float*)d_in[2];   // [32,1024]
    const float* alpha = (const float*)d_in[3];   // scalar
    const float* beta  = (const float*)d_in[4];   // scalar
    float* Out = (float*)d_out;

    geom_proj_kernel<<<256, 128>>>(H, W);
    bias_update_kernel<<<dim3(528, NB), 128>>>(Bprev, alpha, beta, Out);
}

// round 11
// speedup vs baseline: 2.0901x; 1.0359x over previous
#include <cuda_runtime.h>
#include <cstdint>

#define NB       4
#define NN       2048
#define CLAMP_V  10.0f

typedef unsigned long long ull;

// Partial G (4 d-quarters): [4][NB*NN][32] floats = 4 MB (no allocs allowed)
__device__ __align__(16) float g_Gp[4 * NB * NN * 32];

// ---------------- packed f32x2 helpers (FFMA2 via PTX) ----------------
__device__ __forceinline__ ull ffma2(ull a, ull b, ull c) {
    ull d;
    asm("fma.rn.f32x2 %0, %1, %2, %3;" : "=l"(d) : "l"(a), "l"(b), "l"(c));
    return d;
}
__device__ __forceinline__ ull pack2(float x, float y) {
    ull r;
    asm("mov.b64 %0, {%1, %2};" : "=l"(r) : "f"(x), "f"(y));
    return r;
}
__device__ __forceinline__ float2 unpack2(ull v) {
    float2 f;
    asm("mov.b64 {%0, %1}, %2;" : "=f"(f.x), "=f"(f.y) : "l"(v));
    return f;
}
__device__ __forceinline__ float hadd2(ull v) {
    float2 f = unpack2(v);
    return f.x + f.y;
}
__device__ __forceinline__ uint32_t smem_u32(const void* p) {
    uint32_t a;
    asm("{ .reg .u64 t; cvta.to.shared.u64 t, %1; cvt.u32.u64 %0, t; }" : "=r"(a) : "l"(p));
    return a;
}
__device__ __forceinline__ void cp16(uint32_t dst, const void* src) {
    asm volatile("cp.async.cg.shared.global [%0], [%1], 16;" :: "r"(dst), "l"(src) : "memory");
}
#define CP_COMMIT() asm volatile("cp.async.commit_group;" ::: "memory")
#define CP_WAIT0()  asm volatile("cp.async.wait_group 0;" ::: "memory")

// ============================================================================
// Kernel 1: partial G[q][n][k] = sum_{d in quarter q} H[n][d] * W[k][d]
// 256 blocks (64 row-tiles x 4 d-quarters) x 256 threads (4 warps/SMSP).
// Tile 128 rows x 32 k; chunk = 32 d (16 dpairs), 8 chunks per quarter.
// Micro 4 rows x 4 k (k = kg + 8q strided).
// ============================================================================
#define HROW 18   // ull per H row (16 dpairs + pad 2)
#define WROW 34   // ull per Ws row (32 k + pad 2)

__global__ __launch_bounds__(256)
void geom_proj_kernel(const float* __restrict__ H, const float* __restrict__ W) {
    __shared__ ull Hs[2][128][HROW];
    __shared__ ull Ws[2][16][WROW];

    const int tid  = threadIdx.x;
    const int kg   = tid & 7;          // k = kg + 8q
    const int ty   = tid >> 3;         // rows ty + 32*r  (0..31)
    const int quar = blockIdx.x & 3;
    const int n0   = (blockIdx.x >> 2) * 128;
    const int dbase = quar * 256;      // float offset

    const float4* __restrict__ W4 = (const float4*)W;
    const uint32_t hsb = smem_u32(&Hs[0][0][0]);

    // prologue: cp.async H chunk 0, LDG W chunk 0
    #pragma unroll
    for (int p = 0; p < 4; p++) {
        int idx = tid + 256 * p;       // 0..1023
        int row = idx >> 3, fc = idx & 7;
        cp16(hsb + (uint32_t)(row * HROW + fc * 2) * 8,
             H + (size_t)(n0 + row) * 1024 + dbase + fc * 4);
    }
    CP_COMMIT();

    float4 wr = W4[(tid >> 3) * 256 + quar * 64 + (tid & 7)];

    ull acc[4][4];
    #pragma unroll
    for (int r = 0; r < 4; r++)
        #pragma unroll
        for (int q = 0; q < 4; q++) acc[r][q] = 0ULL;

    #pragma unroll 1
    for (int c = 0; c < 8; c++) {
        const int buf = c & 1;
        CP_WAIT0();
        __syncthreads();

        // transpose-stage W chunk c: Ws[dp][k]
        {
            int k = tid >> 3, fs = tid & 7;
            Ws[buf][fs * 2][k]     = pack2(wr.x, wr.y);
            Ws[buf][fs * 2 + 1][k] = pack2(wr.z, wr.w);
        }

        if (c < 7) {                   // prefetch chunk c+1
            #pragma unroll
            for (int p = 0; p < 4; p++) {
                int idx = tid + 256 * p;
                int row = idx >> 3, fc = idx & 7;
                cp16(hsb + (uint32_t)(((1 - buf) * 128 + row) * HROW + fc * 2) * 8,
                     H + (size_t)(n0 + row) * 1024 + dbase + (c + 1) * 32 + fc * 4);
            }
            CP_COMMIT();
            wr = W4[(tid >> 3) * 256 + quar * 64 + (c + 1) * 8 + (tid & 7)];
        }
        __syncthreads();

        #pragma unroll
        for (int dp2 = 0; dp2 < 8; dp2++) {
            ull w0[4], w1[4];
            #pragma unroll
            for (int q = 0; q < 4; q++) {
                w0[q] = Ws[buf][2 * dp2][kg + 8 * q];
                w1[q] = Ws[buf][2 * dp2 + 1][kg + 8 * q];
            }
            #pragma unroll
            for (int r = 0; r < 4; r++) {
                float4 hv = *(const float4*)&Hs[buf][ty + 32 * r][2 * dp2];
                ull hA = pack2(hv.x, hv.y);
                ull hB = pack2(hv.z, hv.w);
                #pragma unroll
                for (int q = 0; q < 4; q++) {
                    acc[r][q] = ffma2(hA, w0[q], acc[r][q]);
                    acc[r][q] = ffma2(hB, w1[q], acc[r][q]);
                }
            }
        }
    }

    float* __restrict__ Gp = g_Gp + (size_t)quar * (NB * NN * 32);
    #pragma unroll
    for (int r = 0; r < 4; r++) {
        const size_t rb = (size_t)(n0 + ty + 32 * r) * 32;
        #pragma unroll
        for (int q = 0; q < 4; q++)
            Gp[rb + kg + 8 * q] = hadd2(acc[r][q]);
    }
}

// ============================================================================
// Kernel 2: triangular-symmetric EMA bias update, vectorized epilogue.
// Grid (528, 4); 128 threads; 64x64 tile; Gram micro 8(i) x 4(j).
// Phase B: bd = beta*max(dist,0) -> dist_s[i][j] AND dist_t[j][i] (dist_t
// aliases the dead G tiles). Phase C: float4 epilogue, all 16 LDG.128 batched
// (MLP 16), LDS.128 dist reads, STG.128 stores.
// ============================================================================
#define GROW 18    // 16 kpairs + pad 2

__global__ __launch_bounds__(128)
void bias_update_kernel(const float* __restrict__ Bprev,
                        const float* __restrict__ alpha_p,
                        const float* __restrict__ beta_p,
                        float* __restrict__ Out) {
    __shared__ __align__(16) unsigned char gbuf[2][9216];  // Gi | Gj; later dist_t
    __shared__ __align__(16) float dist_s[64][68];
    __shared__ float gsqI[64];
    __shared__ float gsqJ[64];

    ull (*Gi)[GROW] = (ull(*)[GROW])gbuf[0];
    ull (*Gj)[GROW] = (ull(*)[GROW])gbuf[1];
    float (*dist_t)[68] = (float(*)[68])gbuf;              // 64*68*4 = 17408 <= 18432

    const int tid = threadIdx.x;
    const int tx  = tid & 15;      // Gram: j = tx + 16*jj
    const int ty  = tid >> 4;      // Gram: i = ty + 8*ii
    const int b   = blockIdx.y;

    // triangular decode: q -> (ti, tj), tj <= ti
    const int q = blockIdx.x;
    int ti = (int)((sqrtf(8.0f * (float)q + 1.0f) - 1.0f) * 0.5f);
    while ((ti + 1) * (ti + 2) / 2 <= q) ti++;
    while (ti * (ti + 1) / 2 > q) ti--;
    const int tj = q - ti * (ti + 1) / 2;
    const int i0 = ti * 64;
    const int j0 = tj * 64;
    const bool offd = (ti != tj);

    // ---- stage G tiles (sum of the four d-split partials)
    const float4* __restrict__ P0 = (const float4*)g_Gp;
    const float4* __restrict__ P1 = P0 + (NB * NN * 32) / 4;
    const float4* __restrict__ P2 = P1 + (NB * NN * 32) / 4;
    const float4* __restrict__ P3 = P2 + (NB * NN * 32) / 4;
    const size_t baseI = ((size_t)b * NN + i0) * 8;   // float4 units (8/row)
    const size_t baseJ = ((size_t)b * NN + j0) * 8;

    #pragma unroll
    for (int p = 0; p < 4; p++) {
        int idx = tid + 128 * p;               // 0..511
        int row = idx >> 3, fc = idx & 7;
        float4 a0 = P0[baseI + idx];
        float4 a1 = P1[baseI + idx];
        float4 a2 = P2[baseI + idx];
        float4 a3 = P3[baseI + idx];
        float4 s;
        s.x = (a0.x + a1.x) + (a2.x + a3.x);
        s.y = (a0.y + a1.y) + (a2.y + a3.y);
        s.z = (a0.z + a1.z) + (a2.z + a3.z);
        s.w = (a0.w + a1.w) + (a2.w + a3.w);
        *(float4*)&Gi[row][fc * 2] = s;
        float4 b0 = P0[baseJ + idx];
        float4 b1 = P1[baseJ + idx];
        float4 b2 = P2[baseJ + idx];
        float4 b3 = P3[baseJ + idx];
        float4 t;
        t.x = (b0.x + b1.x) + (b2.x + b3.x);
        t.y = (b0.y + b1.y) + (b2.y + b3.y);
        t.z = (b0.z + b1.z) + (b2.z + b3.z);
        t.w = (b0.w + b1.w) + (b2.w + b3.w);
        *(float4*)&Gj[row][fc * 2] = t;
    }
    __syncthreads();

    // ---- row squared-norms
    if (tid < 64) {
        float s = 0.f;
        #pragma unroll
        for (int kk = 0; kk < 16; kk++) {
            float2 v = unpack2(Gi[tid][kk]);
            s += v.x * v.x + v.y * v.y;
        }
        gsqI[tid] = s;
    } else {
        int t = tid - 64;
        float s = 0.f;
        #pragma unroll
        for (int kk = 0; kk < 16; kk++) {
            float2 v = unpack2(Gj[t][kk]);
            s += v.x * v.x + v.y * v.y;
        }
        gsqJ[t] = s;
    }
    __syncthreads();

    // ---- 8x4 Gram micro-tile (full operand staging)
    ull acc[8][4];
    #pragma unroll
    for (int ii = 0; ii < 8; ii++)
        #pragma unroll
        for (int jj = 0; jj < 4; jj++) acc[ii][jj] = 0ULL;

    #pragma unroll
    for (int kk2 = 0; kk2 < 8; kk2++) {
        ull a0[8], a1[8], b0[4], b1[4];
        #pragma unroll
        for (int ii = 0; ii < 8; ii++) {
            float4 t = *(const float4*)&Gi[ty + 8 * ii][kk2 * 2];
            a0[ii] = pack2(t.x, t.y);
            a1[ii] = pack2(t.z, t.w);
        }
        #pragma unroll
        for (int jj = 0; jj < 4; jj++) {
            float4 t = *(const float4*)&Gj[tx + 16 * jj][kk2 * 2];
            b0[jj] = pack2(t.x, t.y);
            b1[jj] = pack2(t.z, t.w);
        }
        #pragma unroll
        for (int ii = 0; ii < 8; ii++)
            #pragma unroll
            for (int jj = 0; jj < 4; jj++) {
                acc[ii][jj] = ffma2(a0[ii], b0[jj], acc[ii][jj]);
                acc[ii][jj] = ffma2(a1[ii], b1[jj], acc[ii][jj]);
            }
    }

    const float alpha = __ldg(alpha_p);
    const float beta  = __ldg(beta_p);

    // ---- Phase B: bd = beta*max(dist,0) into registers
    float bd[8][4];
    #pragma unroll
    for (int ii = 0; ii < 8; ii++) {
        const float si = gsqI[ty + 8 * ii];
        #pragma unroll
        for (int jj = 0; jj < 4; jj++) {
            float g = hadd2(acc[ii][jj]);
            float dist = si + gsqJ[tx + 16 * jj] - 2.0f * g;
            bd[ii][jj] = beta * fmaxf(dist, 0.0f);
        }
    }
    __syncthreads();               // all Gram smem reads done (dist_t aliases G)

    #pragma unroll
    for (int ii = 0; ii < 8; ii++) {
        const int il = ty + 8 * ii;
        #pragma unroll
        for (int jj = 0; jj < 4; jj++) {
            const int jl = tx + 16 * jj;
            dist_s[il][jl] = bd[ii][jj];
            if (offd) dist_t[jl][il] = bd[ii][jj];
        }
    }
    __syncthreads();

    // ---- Phase C: vectorized epilogue; all loads batched (MLP up to 16)
    const int c4 = tid & 15;       // float4 column
    const int rg = tid >> 4;       // row = rg + 8*rr
    const size_t obase = (size_t)b * NN * NN;

    float4 bp1[8], bp2[8];
    #pragma unroll
    for (int rr = 0; rr < 8; rr++) {
        const int row = rg + 8 * rr;
        bp1[rr] = __ldg((const float4*)(Bprev + obase + (size_t)(i0 + row) * NN + j0 + 4 * c4));
    }
    if (offd) {
        #pragma unroll
        for (int rr = 0; rr < 8; rr++) {
            const int row = rg + 8 * rr;
            bp2[rr] = __ldg((const float4*)(Bprev + obase + (size_t)(j0 + row) * NN + i0 + 4 * c4));
        }
    }

    #pragma unroll
    for (int rr = 0; rr < 8; rr++) {
        const int row = rg + 8 * rr;
        float4 d = *(const float4*)&dist_s[row][4 * c4];
        float4 v;
        v.x = fminf(fmaxf(alpha * bp1[rr].x - d.x, -CLAMP_V), CLAMP_V);
        v.y = fminf(fmaxf(alpha * bp1[rr].y - d.y, -CLAMP_V), CLAMP_V);
        v.z = fminf(fmaxf(alpha * bp1[rr].z - d.z, -CLAMP_V), CLAMP_V);
        v.w = fminf(fmaxf(alpha * bp1[rr].w - d.w, -CLAMP_V), CLAMP_V);
        *(float4*)(Out + obase + (size_t)(i0 + row) * NN + j0 + 4 * c4) = v;
    }
    if (offd) {
        #pragma unroll
        for (int rr = 0; rr < 8; rr++) {
            const int row = rg + 8 * rr;
            float4 d = *(const float4*)&dist_t[row][4 * c4];
            float4 v;
            v.x = fminf(fmaxf(alpha * bp2[rr].x - d.x, -CLAMP_V), CLAMP_V);
            v.y = fminf(fmaxf(alpha * bp2[rr].y - d.y, -CLAMP_V), CLAMP_V);
            v.z = fminf(fmaxf(alpha * bp2[rr].z - d.z, -CLAMP_V), CLAMP_V);
            v.w = fminf(fmaxf(alpha * bp2[rr].w - d.w, -CLAMP_V), CLAMP_V);
            *(float4*)(Out + obase + (size_t)(j0 + row) * NN + i0 + 4 * c4) = v;
        }
    }
}

// ============================================================================
extern "C" void kernel_launch(void* const* d_in, const int* in_sizes, int n_in,
                              void* d_out, int out_size) {
    const float* H     = (const float*)d_in[0];   // [4,2048,1024]
    const float* Bprev = (const float*)d_in[1];   // [4,2048,2048]
    const float* W     = (const float*)d_in[2];   // [32,1024]
    const float* alpha = (const float*)d_in[3];   // scalar
    const float* beta  = (const float*)d_in[4];   // scalar
    float* Out = (float*)d_out;

    geom_proj_kernel<<<256, 256>>>(H, W);
    bias_update_kernel<<<dim3(528, NB), 128>>>(Bprev, alpha, beta, Out);
}